// round 4
// baseline (speedup 1.0000x reference)
#include <cuda_runtime.h>

// 3D inverse Haar DWT via local 2x2x2 signed butterfly (S is the banded Haar
// synthesis operator: out[2m] = r*(lo[m]-hi[m]), out[2m+1] = r*(lo[m]+hi[m])).
//
// Round-3 change vs round-2 (36.9us kernel, DRAM=71.5%):
//   * 2 coarse voxels per thread, grid-strided by TOTAL/2 so every LDG.128 /
//     STG.128 stays perfectly warp-coalesced -> 8 independent loads + 8
//     independent stores in flight per thread (2x MLP).
//   * __ldcs / __stcs streaming hints: both streams are single-touch, keep
//     them out of L2 residency.
// Goal: push dram__cycles_active from 71.5% toward ~85%.

#define HALF_N 128
#define TOTAL_VOX (HALF_N * HALF_N * HALF_N)  // 2,097,152
#define R3 0.35355339059327378f               // 2^{-3/2}

struct V16 { float2 v[8]; };

__device__ __forceinline__ V16 load_voxel(const float4* __restrict__ p)
{
    float4 q0 = __ldcs(p + 0);
    float4 q1 = __ldcs(p + 1);
    float4 q2 = __ldcs(p + 2);
    float4 q3 = __ldcs(p + 3);
    V16 r;
    r.v[0] = make_float2(q0.x, q0.y); r.v[1] = make_float2(q0.z, q0.w);
    r.v[2] = make_float2(q1.x, q1.y); r.v[3] = make_float2(q1.z, q1.w);
    r.v[4] = make_float2(q2.x, q2.y); r.v[5] = make_float2(q2.z, q2.w);
    r.v[6] = make_float2(q3.x, q3.y); r.v[7] = make_float2(q3.z, q3.w);
    return r;
}

__device__ __forceinline__ void butterfly(V16& x)
{
    // Stage 1: axis-3
    float2 u[8];
    #pragma unroll
    for (int g = 0; g < 4; g++) {
        float2 L = x.v[2 * g + 0], H = x.v[2 * g + 1];
        u[2 * g + 0] = make_float2(L.x - H.x, L.y - H.y);
        u[2 * g + 1] = make_float2(L.x + H.x, L.y + H.y);
    }
    // Stage 2: axis-2
    float2 w[8];
    #pragma unroll
    for (int s1 = 0; s1 < 2; s1++)
        #pragma unroll
        for (int d = 0; d < 2; d++) {
            float2 L = u[s1 * 4 + d], H = u[s1 * 4 + 2 + d];
            w[s1 * 4 + d]     = make_float2(L.x - H.x, L.y - H.y);
            w[s1 * 4 + 2 + d] = make_float2(L.x + H.x, L.y + H.y);
        }
    // Stage 3: axis-1
    #pragma unroll
    for (int e = 0; e < 4; e++) {
        float2 L = w[e], H = w[4 + e];
        x.v[e]     = make_float2(L.x - H.x, L.y - H.y);
        x.v[4 + e] = make_float2(L.x + H.x, L.y + H.y);
    }
}

__device__ __forceinline__ void store_voxel(float* __restrict__ out, int t, const V16& x)
{
    const int k = t & (HALF_N - 1);
    const int j = (t >> 7) & (HALF_N - 1);
    const int i = t >> 14;
    #pragma unroll
    for (int a = 0; a < 2; a++)
        #pragma unroll
        for (int b = 0; b < 2; b++) {
            const size_t off =
                ((size_t)(2 * i + a) * 256 + (size_t)(2 * j + b)) * 512 + (size_t)(4 * k);
            float2 e0 = x.v[a * 4 + b * 2 + 0];
            float2 e1 = x.v[a * 4 + b * 2 + 1];
            __stcs(reinterpret_cast<float4*>(out + off),
                   make_float4(R3 * e0.x, R3 * e0.y, R3 * e1.x, R3 * e1.y));
        }
}

__global__ void __launch_bounds__(256)
idwt3d_haar_kernel(const float* __restrict__ in, float* __restrict__ out)
{
    const int t0 = blockIdx.x * blockDim.x + threadIdx.x;   // < TOTAL/2
    const int t1 = t0 + TOTAL_VOX / 2;

    const float4* __restrict__ base = reinterpret_cast<const float4*>(in);

    // Issue all 8 loads before any dependent compute (max MLP).
    V16 x0 = load_voxel(base + (size_t)t0 * 4);
    V16 x1 = load_voxel(base + (size_t)t1 * 4);

    butterfly(x0);
    butterfly(x1);

    store_voxel(out, t0, x0);
    store_voxel(out, t1, x1);
}

extern "C" void kernel_launch(void* const* d_in, const int* in_sizes, int n_in,
                              void* d_out, int out_size)
{
    const float* x = (const float*)d_in[0];   // [1,128,128,128,16]
    float* out = (float*)d_out;               // [1,256,256,256,2]

    const int threads = 256;
    const int blocks = (TOTAL_VOX / 2) / threads;  // 4096
    idwt3d_haar_kernel<<<blocks, threads>>>(x, out);
}

// round 5
// speedup vs baseline: 1.0092x; 1.0092x over previous
#include <cuda_runtime.h>

// 3D inverse Haar DWT via local 2x2x2 signed butterfly.
// S (Haar synthesis) == out[2m] = r*(lo[m]-hi[m]); out[2m+1] = r*(lo[m]+hi[m]).
// Separable over 3 axes -> each output 2x2x2 block is a signed butterfly of
// the 8 octant coefficients at one coarse voxel, scaled r^3.
//
// R4 vs R2 (best, 36.9us kernel, ~7.3TB/s app BW = 91% of HBM spec):
//   * input loads as 2x 256-bit ld.global.nc.v8.f32 (sm_100a LDG.E.256)
//     instead of 4x LDG.128 — halves load instruction count / L1tex
//     wavefronts. Everything else identical to R2 (1 voxel/thread, plain
//     STG.128 stores, block=256). Traffic is already at the 268MB floor.

#define HALF_N 128
#define TOTAL_VOX (HALF_N * HALF_N * HALF_N)
#define R3 0.35355339059327378f  // 2^{-3/2}

__global__ void __launch_bounds__(256, 8)
idwt3d_haar_kernel(const float* __restrict__ in, float* __restrict__ out)
{
    const int t = blockIdx.x * blockDim.x + threadIdx.x;   // coarse voxel id
    const int k = t & (HALF_N - 1);
    const int j = (t >> 7) & (HALF_N - 1);
    const int i = t >> 14;

    // Load 16 contiguous floats (64B, 32B-aligned) via two 256-bit loads.
    const float* __restrict__ p = in + (size_t)t * 16;
    float f0, f1, f2, f3, f4, f5, f6, f7;
    float f8, f9, f10, f11, f12, f13, f14, f15;
    asm volatile("ld.global.nc.v8.f32 {%0,%1,%2,%3,%4,%5,%6,%7}, [%8];"
                 : "=f"(f0), "=f"(f1), "=f"(f2), "=f"(f3),
                   "=f"(f4), "=f"(f5), "=f"(f6), "=f"(f7)
                 : "l"(p));
    asm volatile("ld.global.nc.v8.f32 {%0,%1,%2,%3,%4,%5,%6,%7}, [%8];"
                 : "=f"(f8), "=f"(f9), "=f"(f10), "=f"(f11),
                   "=f"(f12), "=f"(f13), "=f"(f14), "=f"(f15)
                 : "l"(p + 8));

    // v[sb] = {ch0, ch1}, sb = s1*4 + s2*2 + s3  (L=0, H=1 per axis)
    float2 v[8];
    v[0] = make_float2(f0,  f1);  v[1] = make_float2(f2,  f3);
    v[2] = make_float2(f4,  f5);  v[3] = make_float2(f6,  f7);
    v[4] = make_float2(f8,  f9);  v[5] = make_float2(f10, f11);
    v[6] = make_float2(f12, f13); v[7] = make_float2(f14, f15);

    // Stage 1: axis-3
    float2 u[8];
    #pragma unroll
    for (int g = 0; g < 4; g++) {
        float2 L = v[2 * g + 0], H = v[2 * g + 1];
        u[2 * g + 0] = make_float2(L.x - H.x, L.y - H.y);
        u[2 * g + 1] = make_float2(L.x + H.x, L.y + H.y);
    }
    // Stage 2: axis-2
    float2 w[8];
    #pragma unroll
    for (int s1 = 0; s1 < 2; s1++)
        #pragma unroll
        for (int d = 0; d < 2; d++) {
            float2 L = u[s1 * 4 + d], H = u[s1 * 4 + 2 + d];
            w[s1 * 4 + d]     = make_float2(L.x - H.x, L.y - H.y);
            w[s1 * 4 + 2 + d] = make_float2(L.x + H.x, L.y + H.y);
        }
    // Stage 3: axis-1
    float2 rr[8];
    #pragma unroll
    for (int e = 0; e < 4; e++) {
        float2 L = w[e], H = w[4 + e];
        rr[e]     = make_float2(L.x - H.x, L.y - H.y);
        rr[4 + e] = make_float2(L.x + H.x, L.y + H.y);
    }

    // Store: out[(2i+a), (2j+b), 2k+d, c]; for fixed (a,b) -> one float4.
    #pragma unroll
    for (int a = 0; a < 2; a++)
        #pragma unroll
        for (int b = 0; b < 2; b++) {
            const size_t off =
                ((size_t)(2 * i + a) * 256 + (size_t)(2 * j + b)) * 512 + (size_t)(4 * k);
            float2 e0 = rr[a * 4 + b * 2 + 0];
            float2 e1 = rr[a * 4 + b * 2 + 1];
            *reinterpret_cast<float4*>(out + off) =
                make_float4(R3 * e0.x, R3 * e0.y, R3 * e1.x, R3 * e1.y);
        }
}

extern "C" void kernel_launch(void* const* d_in, const int* in_sizes, int n_in,
                              void* d_out, int out_size)
{
    const float* x = (const float*)d_in[0];   // [1,128,128,128,16]
    float* out = (float*)d_out;               // [1,256,256,256,2]

    const int threads = 256;
    const int blocks = TOTAL_VOX / threads;   // 8192
    idwt3d_haar_kernel<<<blocks, threads>>>(x, out);
}